// round 16
// baseline (speedup 1.0000x reference)
#include <cuda_runtime.h>
#include <cuda_fp16.h>
#include <cuda_bf16.h>

// ResidualGridVolume: out[n,c] = trilinear((base+detail)[c], xyz[n]/1.5), C=28, R=128.
//
// R15 was an infra failure (same "container failed twice" seen on the empty
// stub in R2); resubmitting the template-fixed channel-split design.
//
// Design: CHANNEL-split into two 64 MB half-volumes (16 fp16 ch = 32 B/voxel,
// one sector, fully aligned). Measured random-gather miss vs footprint:
// 134 MB -> ~68%, 112 MB -> ~48% (thrash); 64 MB = 0.51x L2 -> warm regime.
// Every point active in BOTH passes (pass A -> out ch 0..15, pass B ->
// ch 16..27): no wasted warps (unlike z-split/binning, which lose).
// Schedule fuseA -> sampleA -> fuseB -> sampleB keeps each half L2-warm from
// its fuse's stores. Quad-cooperative gather (4 thr/pt, 8B chunks).
// R14 bug fixed: half-volume selected via template param INSIDE device code
// (host-side __device__-symbol addresses are invalid).

static constexpr int R   = 128;
static constexpr int R3  = R * R * R;     // 2,097,152 voxels
static constexpr int CH  = 28;            // output channels
static constexpr int HC  = 16;            // channels per half-volume (padded)

// Two 64 MB half-volumes: __device__ globals (no runtime allocation).
__device__ __align__(256) __half g_volA[(size_t)R3 * HC]; // density + sh[0..14]
__device__ __align__(256) __half g_volB[(size_t)R3 * HC]; // sh[15..26] + 4 pad

// ---------------------------------------------------------------------------
// Fuse A: volA[v] = {base_density+detail_density, (base_sh+detail_sh)[0..14]}
// ---------------------------------------------------------------------------
__global__ void fuseA_kernel(const float* __restrict__ base_density,
                             const float* __restrict__ base_sh,
                             const float* __restrict__ detail_density,
                             const float* __restrict__ detail_sh) {
    int v = blockIdx.x * blockDim.x + threadIdx.x;
    if (v >= R3) return;

    __half h[HC];
    h[0] = __float2half_rn(__ldcs(base_density + v) + __ldcs(detail_density + v));
#pragma unroll
    for (int c = 0; c < 15; c++) {
        size_t off = (size_t)c * R3 + (size_t)v;
        h[c + 1] = __float2half_rn(__ldcs(base_sh + off) + __ldcs(detail_sh + off));
    }
    uint4* dst = reinterpret_cast<uint4*>(g_volA + (size_t)v * HC);
    dst[0] = reinterpret_cast<const uint4*>(h)[0];
    dst[1] = reinterpret_cast<const uint4*>(h)[1];
}

// ---------------------------------------------------------------------------
// Fuse B: volB[v] = {(base_sh+detail_sh)[15..26], 0,0,0,0}
// ---------------------------------------------------------------------------
__global__ void fuseB_kernel(const float* __restrict__ base_sh,
                             const float* __restrict__ detail_sh) {
    int v = blockIdx.x * blockDim.x + threadIdx.x;
    if (v >= R3) return;

    __half h[HC];
#pragma unroll
    for (int c = 0; c < 12; c++) {
        size_t off = (size_t)(15 + c) * R3 + (size_t)v;
        h[c] = __float2half_rn(__ldcs(base_sh + off) + __ldcs(detail_sh + off));
    }
#pragma unroll
    for (int c = 12; c < HC; c++) h[c] = __float2half_rn(0.0f);

    uint4* dst = reinterpret_cast<uint4*>(g_volB + (size_t)v * HC);
    dst[0] = reinterpret_cast<const uint4*>(h)[0];
    dst[1] = reinterpret_cast<const uint4*>(h)[1];
}

// ---------------------------------------------------------------------------
// Sample one half-volume (PASS=0 -> volA / out ch 0..15, PASS=1 -> volB /
// out ch 16..27). Quad-cooperative: 4 threads per point; thread j = tid&3
// owns half-volume channels 4j..4j+3 (one 8B-aligned uint2 per corner).
// Output float4 at byte 112p + 64*PASS + 16j -> always 16B-aligned.
// PASS=1, j==3 covers padding channels only -> store skipped.
// ---------------------------------------------------------------------------
template <int PASS>
__global__ void __launch_bounds__(256)
sample_half_kernel(const float* __restrict__ xyz, float* __restrict__ out,
                   int N) {
    int t = blockIdx.x * blockDim.x + threadIdx.x;
    int p = t >> 2;          // point index (8 points per warp)
    int j = t & 3;           // chunk index
    if (p >= N) return;

    const __half* vol = (PASS == 0) ? g_volA : g_volB;  // device-side symbol ref

    // Quad-broadcast reads of this point's coords (streaming).
    const float inv_bound = 1.0f / 1.5f;
    float gx = __ldcs(xyz + 3 * p + 0) * inv_bound;
    float gy = __ldcs(xyz + 3 * p + 1) * inv_bound;
    float gz = __ldcs(xyz + 3 * p + 2) * inv_bound;

    // align_corners=True: pix = (g + 1) * 0.5 * (size - 1)
    float px = (gx + 1.0f) * 0.5f * 127.0f;
    float py = (gy + 1.0f) * 0.5f * 127.0f;
    float pz = (gz + 1.0f) * 0.5f * 127.0f;

    float fx0 = floorf(px), fy0 = floorf(py), fz0 = floorf(pz);
    float fx = px - fx0, fy = py - fy0, fz = pz - fz0;

    // Inputs are interior (|g| <= 0.99); clamps are safety only.
    int x0 = min(max((int)fx0, 0), R - 2);
    int y0 = min(max((int)fy0, 0), R - 2);
    int z0 = min(max((int)fz0, 0), R - 2);

    float wx1 = fx, wx0 = 1.0f - fx;
    float wy1 = fy, wy0 = 1.0f - fy;
    float wz1 = fz, wz0 = 1.0f - fz;

    float w[8];
    w[0] = wz0 * wy0 * wx0;
    w[1] = wz0 * wy0 * wx1;
    w[2] = wz0 * wy1 * wx0;
    w[3] = wz0 * wy1 * wx1;
    w[4] = wz1 * wy0 * wx0;
    w[5] = wz1 * wy0 * wx1;
    w[6] = wz1 * wy1 * wx0;
    w[7] = wz1 * wy1 * wx1;

    const unsigned OX = HC;               // +1 in x (in halves)
    const unsigned OY = R * HC;           // +1 in y
    const unsigned OZ = R * R * HC;       // +1 in z
    unsigned base = (((unsigned)z0 * R + (unsigned)y0) * R + (unsigned)x0) * HC
                    + 4u * (unsigned)j;   // this thread's channel chunk

    unsigned offs[8];
    offs[0] = base;
    offs[1] = base + OX;
    offs[2] = base + OY;
    offs[3] = base + OY + OX;
    offs[4] = base + OZ;
    offs[5] = base + OZ + OX;
    offs[6] = base + OZ + OY;
    offs[7] = base + OZ + OY + OX;

    // Issue all 8 corner loads (MLP = 8), then accumulate.
    uint2 q[8];
#pragma unroll
    for (int k = 0; k < 8; k++)
        q[k] = __ldg(reinterpret_cast<const uint2*>(vol + (size_t)offs[k]));

    float acc0 = 0.f, acc1 = 0.f, acc2 = 0.f, acc3 = 0.f;
#pragma unroll
    for (int k = 0; k < 8; k++) {
        float wk = w[k];
        __half2 h0 = *reinterpret_cast<__half2*>(&q[k].x);
        __half2 h1 = *reinterpret_cast<__half2*>(&q[k].y);
        float2 f0 = __half22float2(h0);
        float2 f1 = __half22float2(h1);
        acc0 = fmaf(wk, f0.x, acc0);
        acc1 = fmaf(wk, f0.y, acc1);
        acc2 = fmaf(wk, f1.x, acc2);
        acc3 = fmaf(wk, f1.y, acc3);
    }

    // Streaming store (evict-first): don't displace the resident half-volume.
    // PASS=0: chunks 0..3 -> ch 0..15. PASS=1: chunks 0..2 -> ch 16..27.
    if (PASS == 0 || j < 3) {
        float4* o = reinterpret_cast<float4*>(out + (size_t)p * CH
                                              + 16 * PASS + 4 * j);
        __stcs(o, make_float4(acc0, acc1, acc2, acc3));
    }
}

// ---------------------------------------------------------------------------
// Launch. Inputs in metadata order:
//   [0] xyz (N*3), [1] base_density (128^3), [2] base_sh (27*128^3),
//   [3] detail_density, [4] detail_sh. Output: float32, N*28.
// Schedule: fuseA -> sampleA -> fuseB -> sampleB so each half-volume is
// L2-warm (just written) when its sample pass runs.
// ---------------------------------------------------------------------------
extern "C" void kernel_launch(void* const* d_in, const int* in_sizes, int n_in,
                              void* d_out, int out_size) {
    const float* xyz            = (const float*)d_in[0];
    const float* base_density   = (const float*)d_in[1];
    const float* base_sh        = (const float*)d_in[2];
    const float* detail_density = (const float*)d_in[3];
    const float* detail_sh      = (const float*)d_in[4];
    float* out = (float*)d_out;

    int N = in_sizes[0] / 3;
    int thr = 256;
    int fuse_blocks = (R3 + thr - 1) / thr;
    long long total = 4LL * N;   // 4 threads per point
    int samp_blocks = (int)((total + thr - 1) / thr);

    fuseA_kernel<<<fuse_blocks, thr>>>(base_density, base_sh,
                                       detail_density, detail_sh);
    sample_half_kernel<0><<<samp_blocks, thr>>>(xyz, out, N);
    fuseB_kernel<<<fuse_blocks, thr>>>(base_sh, detail_sh);
    sample_half_kernel<1><<<samp_blocks, thr>>>(xyz, out, N);
}

// round 17
// speedup vs baseline: 1.2030x; 1.2030x over previous
#include <cuda_runtime.h>
#include <cuda_fp16.h>
#include <cuda_bf16.h>

// ResidualGridVolume: out[n,c] = trilinear((base+detail)[c], xyz[n]/1.5), C=28, R=128.
//
// Consolidated learnings (R3..R16):
//  - fp16 voxel-major volume + quad-cooperative gather (R5) is the best
//    measured structure: 252.3 us (fuse 93 + sample 160).
//  - Multi-pass schemes ALL lose: z-split/binning (random point order keeps
//    warps active), channel-split (flat footprint->miss curve: 134 MB ~68%,
//    112 MB ~48%, 64 MB ~still high; each pass re-pays ~55 us sweep cost).
//  - evict_last policy is a no-op without the (banned) persisting-L2 carveout.
// This round: R5 EXACTLY + evict_first cache policy on the STREAMING traffic
// (output stores, xyz loads). evict_first needs no set-aside -- it demotes
// stream lines in the normal pool, so default replacement retains volume
// lines instead of the ~1.75M write-allocated output lines.

static constexpr int R   = 128;
static constexpr int R3  = R * R * R;     // 2,097,152 voxels
static constexpr int CH  = 28;            // 1 density + 27 SH
static constexpr int CSB = 32;            // padded channel stride (halves) = 64 B

// 134 MB scratch: __device__ global (no runtime allocation).
__device__ __align__(256) __half g_volh[(size_t)R3 * CSB];

// ---- evict_first cache-policy helpers (streaming traffic demotion) --------
__device__ __forceinline__ unsigned long long evict_first_policy() {
    unsigned long long pol;
    asm("createpolicy.fractional.L2::evict_first.b64 %0, 1.0;" : "=l"(pol));
    return pol;
}
__device__ __forceinline__ float ld_stream_f32(const float* p,
                                               unsigned long long pol) {
    float v;
    asm volatile("ld.global.L2::cache_hint.f32 %0, [%1], %2;"
                 : "=f"(v) : "l"(p), "l"(pol));
    return v;
}
__device__ __forceinline__ void st_stream_f32x4(float* p, float a, float b,
                                                float c, float d,
                                                unsigned long long pol) {
    asm volatile("st.global.L2::cache_hint.v4.f32 [%0], {%1,%2,%3,%4}, %5;"
                 :: "l"(p), "f"(a), "f"(b), "f"(c), "f"(d), "l"(pol)
                 : "memory");
}

// ---------------------------------------------------------------------------
// Kernel 1: fuse base+detail -> fp16, voxel-major, 64B-padded voxels.
// Streaming input reads (__ldcs); normal stores leave the volume in L2.
// ---------------------------------------------------------------------------
__global__ void fuse_transpose_kernel(const float* __restrict__ base_density,
                                      const float* __restrict__ base_sh,
                                      const float* __restrict__ detail_density,
                                      const float* __restrict__ detail_sh) {
    int v = blockIdx.x * blockDim.x + threadIdx.x;
    if (v >= R3) return;

    __half h[CSB];
    h[0] = __float2half_rn(__ldcs(base_density + v) + __ldcs(detail_density + v));
#pragma unroll
    for (int c = 0; c < 27; c++) {
        size_t off = (size_t)c * R3 + (size_t)v;
        h[c + 1] = __float2half_rn(__ldcs(base_sh + off) + __ldcs(detail_sh + off));
    }
#pragma unroll
    for (int c = CH; c < CSB; c++) h[c] = __float2half_rn(0.0f);

    uint4* dst = reinterpret_cast<uint4*>(g_volh + (size_t)v * CSB);
#pragma unroll
    for (int i = 0; i < 4; i++)
        dst[i] = reinterpret_cast<const uint4*>(h)[i];
}

// ---------------------------------------------------------------------------
// Kernel 2: quad-cooperative trilinear gather (R5 structure). 4 threads per
// point; thread j = tid&3 owns 16B chunk j (channels 8j..8j+7). Volume loads
// plain __ldg (normal L2 priority); xyz loads and output stores demoted to
// evict_first so they don't churn the volume out of L2.
// ---------------------------------------------------------------------------
__global__ void __launch_bounds__(256)
sample_kernel(const float* __restrict__ xyz, float* __restrict__ out, int N) {
    int t = blockIdx.x * blockDim.x + threadIdx.x;
    int p = t >> 2;          // point index (8 points per warp)
    int j = t & 3;           // chunk index
    if (p >= N) return;

    unsigned long long pol = evict_first_policy();

    // Quad-broadcast reads of this point's coords (evict_first).
    const float inv_bound = 1.0f / 1.5f;
    float gx = ld_stream_f32(xyz + 3 * p + 0, pol) * inv_bound;
    float gy = ld_stream_f32(xyz + 3 * p + 1, pol) * inv_bound;
    float gz = ld_stream_f32(xyz + 3 * p + 2, pol) * inv_bound;

    // align_corners=True: pix = (g + 1) * 0.5 * (size - 1)
    float px = (gx + 1.0f) * 0.5f * 127.0f;
    float py = (gy + 1.0f) * 0.5f * 127.0f;
    float pz = (gz + 1.0f) * 0.5f * 127.0f;

    float fx0 = floorf(px), fy0 = floorf(py), fz0 = floorf(pz);
    float fx = px - fx0, fy = py - fy0, fz = pz - fz0;

    // Inputs are interior (|g| <= 0.99); clamps are safety only.
    int x0 = min(max((int)fx0, 0), R - 2);
    int y0 = min(max((int)fy0, 0), R - 2);
    int z0 = min(max((int)fz0, 0), R - 2);

    float wx1 = fx, wx0 = 1.0f - fx;
    float wy1 = fy, wy0 = 1.0f - fy;
    float wz1 = fz, wz0 = 1.0f - fz;

    float w[8];
    w[0] = wz0 * wy0 * wx0;
    w[1] = wz0 * wy0 * wx1;
    w[2] = wz0 * wy1 * wx0;
    w[3] = wz0 * wy1 * wx1;
    w[4] = wz1 * wy0 * wx0;
    w[5] = wz1 * wy0 * wx1;
    w[6] = wz1 * wy1 * wx0;
    w[7] = wz1 * wy1 * wx1;

    const unsigned OX = CSB;               // +1 in x (in halves)
    const unsigned OY = R * CSB;           // +1 in y
    const unsigned OZ = R * R * CSB;       // +1 in z
    unsigned base = (((unsigned)z0 * R + (unsigned)y0) * R + (unsigned)x0) * CSB;

    unsigned offs[8];
    offs[0] = base;
    offs[1] = base + OX;
    offs[2] = base + OY;
    offs[3] = base + OY + OX;
    offs[4] = base + OZ;
    offs[5] = base + OZ + OX;
    offs[6] = base + OZ + OY;
    offs[7] = base + OZ + OY + OX;

    // Issue all 8 corner loads (MLP = 8), then accumulate.
    uint4 q[8];
#pragma unroll
    for (int k = 0; k < 8; k++)
        q[k] = __ldg(reinterpret_cast<const uint4*>(g_volh + (size_t)offs[k]) + j);

    float acc[8];
#pragma unroll
    for (int a = 0; a < 8; a++) acc[a] = 0.0f;

#pragma unroll
    for (int k = 0; k < 8; k++) {
        float wk = w[k];
        const __half2* h2 = reinterpret_cast<const __half2*>(&q[k]);
#pragma unroll
        for (int m = 0; m < 4; m++) {
            float2 f = __half22float2(h2[m]);
            acc[2 * m + 0] = fmaf(wk, f.x, acc[2 * m + 0]);
            acc[2 * m + 1] = fmaf(wk, f.y, acc[2 * m + 1]);
        }
    }

    // Output row = 112 B at out + p*28; chunk j covers channels 8j..8j+7
    // (j==3: only 24..27). All float4 stores 16B-aligned, evict_first.
    float* orow = out + (size_t)p * CH + 8 * j;
    st_stream_f32x4(orow, acc[0], acc[1], acc[2], acc[3], pol);
    if (j < 3)
        st_stream_f32x4(orow + 4, acc[4], acc[5], acc[6], acc[7], pol);
}

// ---------------------------------------------------------------------------
// Launch. Inputs in metadata order:
//   [0] xyz (N*3), [1] base_density (128^3), [2] base_sh (27*128^3),
//   [3] detail_density, [4] detail_sh. Output: float32, N*28.
// ---------------------------------------------------------------------------
extern "C" void kernel_launch(void* const* d_in, const int* in_sizes, int n_in,
                              void* d_out, int out_size) {
    const float* xyz            = (const float*)d_in[0];
    const float* base_density   = (const float*)d_in[1];
    const float* base_sh        = (const float*)d_in[2];
    const float* detail_density = (const float*)d_in[3];
    const float* detail_sh      = (const float*)d_in[4];
    float* out = (float*)d_out;

    int N = in_sizes[0] / 3;
    int thr = 256;

    fuse_transpose_kernel<<<(R3 + thr - 1) / thr, thr>>>(
        base_density, base_sh, detail_density, detail_sh);

    long long total = 4LL * N;   // 4 threads per point
    int blocks = (int)((total + thr - 1) / thr);
    sample_kernel<<<blocks, thr>>>(xyz, out, N);
}